// round 5
// baseline (speedup 1.0000x reference)
#include <cuda_runtime.h>
#include <cstdint>

// Q3 unpack -> float32 output planes.
// Input:  4096x4096 int32; each word holds 10 x 3-bit fields at shifts 27..0.
// Output: [10*4096, 4096] float32 (reference uint8 promoted to f32 by harness).
// Plane k (shift 27-3k) has the input's linear layout at offset k * n_words.
//
// Thread i: load uint4 (words 4i..4i+3), write one float4 per plane:
//   out4[k*nvec + i] = { (float)((w.x>>s)&7), ..., (float)((w.w>>s)&7) }.
// 64MB in + 671MB out, zero reuse -> pure HBM stream; .cs hints both sides.

__global__ void __launch_bounds__(256)
q3_unpack_f32_kernel(const uint4* __restrict__ in,
                     float4* __restrict__ out,
                     int nvec)  // number of uint4 input vectors (= words/4)
{
    int i = blockIdx.x * blockDim.x + threadIdx.x;
    if (i >= nvec) return;

    const uint4 w = __ldcs(in + i);

    float4* o = out + i;
    const size_t plane = (size_t)nvec;  // plane stride in float4 units

#pragma unroll
    for (int k = 0; k < 10; ++k) {
        const int s = 27 - 3 * k;
        float4 v;
        v.x = (float)((w.x >> s) & 7u);
        v.y = (float)((w.y >> s) & 7u);
        v.z = (float)((w.z >> s) & 7u);
        v.w = (float)((w.w >> s) & 7u);
        __stcs(o + (size_t)k * plane, v);
    }
}

extern "C" void kernel_launch(void* const* d_in, const int* in_sizes, int n_in,
                              void* d_out, int out_size)
{
    (void)n_in; (void)out_size;
    const int n_words = in_sizes[0];      // 4096*4096 = 16,777,216
    const int nvec    = n_words >> 2;     // 4,194,304

    const uint4* in = (const uint4*)d_in[0];
    float4* out = (float4*)d_out;

    const int threads = 256;
    const int blocks  = (nvec + threads - 1) / threads;  // 16384
    q3_unpack_f32_kernel<<<blocks, threads>>>(in, out, nvec);
}

// round 6
// speedup vs baseline: 1.0225x; 1.0225x over previous
#include <cuda_runtime.h>
#include <cstdint>

// Q3 unpack -> float32 planes, 256-bit stores (sm_100a st.global.v8.b32).
// Input:  4096x4096 int32; each word holds 10 x 3-bit fields at shifts 27..0.
// Output: [10*4096, 4096] float32; plane k = (float)((w >> (27-3k)) & 7),
// same linear layout as input at element offset k * n_words.
//
// Thread i handles 8 consecutive words (2 x LDG.128) and emits one 32-byte
// v8.b32 store per plane -> 1KB contiguous per warp per plane per store.
// Traffic: 64MB in + 671MB out, zero reuse -> HBM-bound; .cs both sides.

__device__ __forceinline__ void stg_cs_v8(float* p,
                                          float v0, float v1, float v2, float v3,
                                          float v4, float v5, float v6, float v7)
{
    asm volatile(
        "st.global.cs.v8.b32 [%0], {%1, %2, %3, %4, %5, %6, %7, %8};"
        :: "l"(p),
           "r"(__float_as_uint(v0)), "r"(__float_as_uint(v1)),
           "r"(__float_as_uint(v2)), "r"(__float_as_uint(v3)),
           "r"(__float_as_uint(v4)), "r"(__float_as_uint(v5)),
           "r"(__float_as_uint(v6)), "r"(__float_as_uint(v7))
        : "memory");
}

__global__ void __launch_bounds__(256)
q3_unpack_f32_v8_kernel(const uint4* __restrict__ in,
                        float* __restrict__ out,
                        int nvec8)  // number of 8-word groups (= words/8)
{
    int i = blockIdx.x * blockDim.x + threadIdx.x;
    if (i >= nvec8) return;

    const uint4 a = __ldcs(in + 2 * (size_t)i);
    const uint4 b = __ldcs(in + 2 * (size_t)i + 1);

    const size_t plane = (size_t)nvec8 * 8;   // plane stride in floats
    float* o = out + (size_t)i * 8;

#pragma unroll
    for (int k = 0; k < 10; ++k) {
        const int s = 27 - 3 * k;
        stg_cs_v8(o + (size_t)k * plane,
                  (float)((a.x >> s) & 7u), (float)((a.y >> s) & 7u),
                  (float)((a.z >> s) & 7u), (float)((a.w >> s) & 7u),
                  (float)((b.x >> s) & 7u), (float)((b.y >> s) & 7u),
                  (float)((b.z >> s) & 7u), (float)((b.w >> s) & 7u));
    }
}

extern "C" void kernel_launch(void* const* d_in, const int* in_sizes, int n_in,
                              void* d_out, int out_size)
{
    (void)n_in; (void)out_size;
    const int n_words = in_sizes[0];      // 4096*4096 = 16,777,216
    const int nvec8   = n_words >> 3;     // 2,097,152

    const uint4* in = (const uint4*)d_in[0];
    float* out = (float*)d_out;

    const int threads = 256;
    const int blocks  = (nvec8 + threads - 1) / threads;  // 8192
    q3_unpack_f32_v8_kernel<<<blocks, threads>>>(in, out, nvec8);
}